// round 5
// baseline (speedup 1.0000x reference)
#include <cuda_runtime.h>
#include <math.h>

#define N_NODES 10000
#define N_EDGES 640000
#define D_FEAT  128

// ---------------- device scratch (no allocations allowed) ----------------
__device__ float g_inv_norm[N_NODES];
__device__ int   g_count[N_NODES];
__device__ int   g_offsets[N_NODES + 1];
__device__ int   g_cursor[N_NODES];
__device__ int   g_src_sorted[N_EDGES];
__device__ float g_e_buf[N_EDGES];
__device__ int   g_is64;

// index loader: works for int32 or int64 source data
__device__ __forceinline__ int load_idx(const void* p, int i, int is64) {
    if (is64) return (int)((const long long*)p)[i];
    return ((const int*)p)[i];
}

// ---------------- phase 0: detect index width ----------------
// If indices are int64 (< N_NODES), every high 32-bit word is 0.
// If int32, the odd words are random indices (virtually never all zero).
__global__ void detect_kernel(const unsigned int* __restrict__ raw) {
    if (threadIdx.x == 0 && blockIdx.x == 0) {
        unsigned int any = 0;
        for (int i = 0; i < 1024; i++) any |= raw[2 * i + 1];
        g_is64 = (any == 0u) ? 1 : 0;
    }
}

// ---------------- phase A: node inverse norms + zero histogram ----------------
// one warp per node; lane l holds dims [4l, 4l+3]
__global__ void norm_kernel(const float* __restrict__ feat) {
    int gw   = (blockIdx.x * blockDim.x + threadIdx.x) >> 5;
    int lane = threadIdx.x & 31;
    if (gw >= N_NODES) return;
    float4 v = ((const float4*)(feat + (size_t)gw * D_FEAT))[lane];
    float ss = v.x * v.x + v.y * v.y + v.z * v.z + v.w * v.w;
#pragma unroll
    for (int o = 16; o; o >>= 1) ss += __shfl_xor_sync(0xffffffffu, ss, o);
    if (lane == 0) {
        float nrm = sqrtf(ss);
        g_inv_norm[gw] = 1.0f / fmaxf(nrm, 1e-12f);
        g_count[gw] = 0;
    }
}

// ---------------- phase B1: histogram of dst ----------------
__global__ void hist_kernel(const void* __restrict__ dst) {
    int i = blockIdx.x * blockDim.x + threadIdx.x;
    if (i < N_EDGES) {
        int d = load_idx(dst, i, g_is64);
        if ((unsigned)d < (unsigned)N_NODES) atomicAdd(&g_count[d], 1);
    }
}

// ---------------- phase B2: exclusive scan (single block, 1024 threads) ----------------
// Shuffle-based scan: no shared-memory access can ever have a negative index.
__global__ void scan_kernel() {
    __shared__ int wt[33];     // wt[0] = 0 pad; wt[1..32] = per-warp totals
    __shared__ int carry_s;
    int tid  = threadIdx.x;
    int lane = tid & 31;
    int warp = tid >> 5;

    if (tid == 0) { carry_s = 0; wt[0] = 0; }
    __syncthreads();

    for (int base = 0; base < N_NODES; base += 1024) {
        int i = base + tid;
        int v = (i < N_NODES) ? g_count[i] : 0;

        // warp-level inclusive scan
        int x = v;
#pragma unroll
        for (int off = 1; off < 32; off <<= 1) {
            int y = __shfl_up_sync(0xffffffffu, x, off);
            if (lane >= off) x += y;
        }
        if (lane == 31) wt[warp + 1] = x;
        __syncthreads();

        // warp 0 scans the 32 warp totals (indices 1..32 only)
        if (warp == 0) {
            int w = wt[lane + 1];
#pragma unroll
            for (int off = 1; off < 32; off <<= 1) {
                int y = __shfl_up_sync(0xffffffffu, w, off);
                if (lane >= off) w += y;
            }
            wt[lane + 1] = w;
        }
        __syncthreads();

        int excl = carry_s + wt[warp] + (x - v);   // wt index in [0,31], wt[0]==0
        if (i < N_NODES) {
            g_offsets[i] = excl;
            g_cursor[i]  = excl;
        }
        __syncthreads();
        if (tid == 0) carry_s += wt[32];
        __syncthreads();
    }
    if (tid == 0) g_offsets[N_NODES] = carry_s;
}

// ---------------- phase B3: scatter edges into dst-sorted order ----------------
__global__ void scatter_kernel(const void* __restrict__ src,
                               const void* __restrict__ dst) {
    int i = blockIdx.x * blockDim.x + threadIdx.x;
    if (i < N_EDGES) {
        int is64 = g_is64;
        int d = load_idx(dst, i, is64);
        if ((unsigned)d < (unsigned)N_NODES) {
            int pos = atomicAdd(&g_cursor[d], 1);
            if ((unsigned)pos < (unsigned)N_EDGES)
                g_src_sorted[pos] = load_idx(src, i, is64);
        }
    }
}

// ---------------- phase C: per-dst-node softmax attention + aggregation ----------------
// one block of 128 threads (4 warps) per dst node
__global__ void __launch_bounds__(128) agnn_main_kernel(const float* __restrict__ feat,
                                                        const float* __restrict__ beta,
                                                        float* __restrict__ out) {
    int n    = blockIdx.x;
    int tid  = threadIdx.x;
    int warp = tid >> 5;
    int lane = tid & 31;

    int start = g_offsets[n];
    int end   = g_offsets[n + 1];
    int deg   = end - start;

    if (deg == 0) {                       // out is poisoned; must write zeros
        out[(size_t)n * D_FEAT + tid] = 0.0f;
        return;
    }

    __shared__ float s_red[4];
    __shared__ float s_max, s_denom;

    float invd = g_inv_norm[n];
    float b    = beta[0];
    // dst row, lane's 4 dims, reused for every edge
    float4 dv = ((const float4*)(feat + (size_t)n * D_FEAT))[lane];

    // ---- pass 1: per-edge cosine * beta, track max ----
    float lmax = -3.402823466e38f;
    for (int j = start + warp; j < end; j += 4) {
        int s = g_src_sorted[j];
        float4 sv = ((const float4*)(feat + (size_t)s * D_FEAT))[lane];
        float dot = sv.x * dv.x + sv.y * dv.y + sv.z * dv.z + sv.w * dv.w;
#pragma unroll
        for (int o = 16; o; o >>= 1) dot += __shfl_xor_sync(0xffffffffu, dot, o);
        float e = b * dot * invd * g_inv_norm[s];   // same value in all lanes
        if (lane == 0) g_e_buf[j] = e;
        lmax = fmaxf(lmax, e);
    }
    if (lane == 0) s_red[warp] = lmax;
    __syncthreads();
    if (tid == 0) {
        s_max = fmaxf(fmaxf(s_red[0], s_red[1]), fmaxf(s_red[2], s_red[3]));
    }
    __syncthreads();
    float m = s_max;

    // ---- pass 2: exp + sum ----
    float lsum = 0.0f;
    for (int j = start + tid; j < end; j += 128) {
        float ex = __expf(g_e_buf[j] - m);
        g_e_buf[j] = ex;
        lsum += ex;
    }
#pragma unroll
    for (int o = 16; o; o >>= 1) lsum += __shfl_xor_sync(0xffffffffu, lsum, o);
    if (lane == 0) s_red[warp] = lsum;
    __syncthreads();
    if (tid == 0) s_denom = s_red[0] + s_red[1] + s_red[2] + s_red[3];
    __syncthreads();
    float rdenom = 1.0f / s_denom;

    // ---- pass 3: weighted aggregation, thread t owns feature dim t ----
    float acc = 0.0f;
    for (int j = start; j < end; j++) {
        int s   = g_src_sorted[j];
        float p = g_e_buf[j];
        acc += p * feat[(size_t)s * D_FEAT + tid];
    }
    out[(size_t)n * D_FEAT + tid] = acc * rdenom;
}

// ---------------- launch ----------------
extern "C" void kernel_launch(void* const* d_in, const int* in_sizes, int n_in,
                              void* d_out, int out_size) {
    const float* feat = (const float*)d_in[0];
    const void*  src  = d_in[1];
    const void*  dst  = d_in[2];
    const float* beta = (const float*)d_in[3];
    float*       out  = (float*)d_out;

    // 0: detect int32 vs int64 indices
    detect_kernel<<<1, 32>>>((const unsigned int*)dst);
    // A: norms + zero histogram (warp per node)
    {
        int threads = 256;
        int blocks  = (N_NODES * 32 + threads - 1) / threads;
        norm_kernel<<<blocks, threads>>>(feat);
    }
    // B1: histogram
    hist_kernel<<<(N_EDGES + 255) / 256, 256>>>(dst);
    // B2: scan
    scan_kernel<<<1, 1024>>>();
    // B3: scatter
    scatter_kernel<<<(N_EDGES + 255) / 256, 256>>>(src, dst);
    // C: main
    agnn_main_kernel<<<N_NODES, 128>>>(feat, beta, out);
}

// round 6
// speedup vs baseline: 1.1658x; 1.1658x over previous
#include <cuda_runtime.h>
#include <math.h>
#include <float.h>

#define N_NODES 10000
#define N_EDGES 640000
#define D_FEAT  128

// ---------------- device scratch (no allocations allowed) ----------------
__device__ float g_inv_norm[N_NODES];
__device__ int   g_count[N_NODES];
__device__ int   g_offsets[N_NODES + 1];
__device__ int   g_cursor[N_NODES];
__device__ int   g_src_sorted[N_EDGES];
__device__ int   g_is64;

// index loader: works for int32 or int64 source data
__device__ __forceinline__ int load_idx(const void* p, int i, int is64) {
    if (is64) return (int)((const long long*)p)[i];
    return ((const int*)p)[i];
}

// ---------------- phase 0: detect index width (parallel) ----------------
// If indices are int64 (< N_NODES), every high 32-bit word is 0.
// If int32, the odd words are random node indices (never all zero over 1024).
__global__ void detect_kernel(const unsigned int* __restrict__ raw) {
    int lane = threadIdx.x & 31;
    unsigned int local = 0;
#pragma unroll
    for (int k = 0; k < 32; k++) local |= raw[2 * (lane + 32 * k) + 1];
    unsigned int any = __any_sync(0xffffffffu, local != 0u);
    if (lane == 0) g_is64 = any ? 0 : 1;
}

// ---------------- phase A: node inverse norms + zero histogram ----------------
__global__ void norm_kernel(const float* __restrict__ feat) {
    int gw   = (blockIdx.x * blockDim.x + threadIdx.x) >> 5;
    int lane = threadIdx.x & 31;
    if (gw >= N_NODES) return;
    float4 v = ((const float4*)(feat + (size_t)gw * D_FEAT))[lane];
    float ss = v.x * v.x + v.y * v.y + v.z * v.z + v.w * v.w;
#pragma unroll
    for (int o = 16; o; o >>= 1) ss += __shfl_xor_sync(0xffffffffu, ss, o);
    if (lane == 0) {
        float nrm = sqrtf(ss);
        g_inv_norm[gw] = 1.0f / fmaxf(nrm, 1e-12f);
        g_count[gw] = 0;
    }
}

// ---------------- phase B1: histogram of dst ----------------
__global__ void hist_kernel(const void* __restrict__ dst) {
    int i = blockIdx.x * blockDim.x + threadIdx.x;
    if (i < N_EDGES) {
        int d = load_idx(dst, i, g_is64);
        if ((unsigned)d < (unsigned)N_NODES) atomicAdd(&g_count[d], 1);
    }
}

// ---------------- phase B2: thread-coarsened exclusive scan ----------------
// 1000 active threads x 10 elements; one block, ~3 sync phases total.
__global__ void scan_kernel() {
    const int PER = 10;
    __shared__ int wt[33];                 // wt[0]=0 pad; wt[1..32]=warp totals
    int tid  = threadIdx.x;
    int lane = tid & 31;
    int warp = tid >> 5;
    int base = tid * PER;
    bool active = (base < N_NODES);

    int vals[PER];
    int tot = 0;
    if (active) {
#pragma unroll
        for (int k = 0; k < PER; k++) { vals[k] = g_count[base + k]; tot += vals[k]; }
    }

    // warp inclusive scan of per-thread totals
    int x = tot;
#pragma unroll
    for (int off = 1; off < 32; off <<= 1) {
        int y = __shfl_up_sync(0xffffffffu, x, off);
        if (lane >= off) x += y;
    }
    if (tid == 0) wt[0] = 0;
    if (lane == 31) wt[warp + 1] = x;
    __syncthreads();
    if (warp == 0) {
        int w = wt[lane + 1];
#pragma unroll
        for (int off = 1; off < 32; off <<= 1) {
            int y = __shfl_up_sync(0xffffffffu, w, off);
            if (lane >= off) w += y;
        }
        wt[lane + 1] = w;
    }
    __syncthreads();

    int run = wt[warp] + (x - tot);        // exclusive offset for this thread's chunk
    if (active) {
#pragma unroll
        for (int k = 0; k < PER; k++) {
            g_offsets[base + k] = run;
            g_cursor[base + k]  = run;
            run += vals[k];
        }
    }
    if (tid == 0) g_offsets[N_NODES] = wt[32];
}

// ---------------- phase B3: scatter edges into dst-sorted order ----------------
__global__ void scatter_kernel(const void* __restrict__ src,
                               const void* __restrict__ dst) {
    int i = blockIdx.x * blockDim.x + threadIdx.x;
    if (i < N_EDGES) {
        int is64 = g_is64;
        int d = load_idx(dst, i, is64);
        if ((unsigned)d < (unsigned)N_NODES) {
            int pos = atomicAdd(&g_cursor[d], 1);
            if ((unsigned)pos < (unsigned)N_EDGES)
                g_src_sorted[pos] = load_idx(src, i, is64);
        }
    }
}

// ---------------- phase C: single-pass online-softmax attention ----------------
// One block of 128 threads (4 warps) per dst node. Each warp streams its share
// of edges once, keeping running (max, sum, acc[float4/lane]) in registers.
// Halves feat L2 traffic vs the 3-pass version; no global e-buffer.
__global__ void __launch_bounds__(128) agnn_fused_kernel(const float* __restrict__ feat,
                                                         const float* __restrict__ beta,
                                                         float* __restrict__ out) {
    int n    = blockIdx.x;
    int tid  = threadIdx.x;
    int warp = tid >> 5;
    int lane = tid & 31;

    int start = g_offsets[n];
    int end   = g_offsets[n + 1];

    if (end == start) {                    // out is poisoned; must write zeros
        out[(size_t)n * D_FEAT + tid] = 0.0f;
        return;
    }

    float invd = g_inv_norm[n];
    float b    = beta[0];
    float4 dv  = ((const float4*)(feat + (size_t)n * D_FEAT))[lane];

    float  m_w = -FLT_MAX;
    float  s_w = 0.0f;
    float4 acc = make_float4(0.f, 0.f, 0.f, 0.f);

    for (int j = start + warp; j < end; j += 4) {
        int s = g_src_sorted[j];
        float4 sv = ((const float4*)(feat + (size_t)s * D_FEAT))[lane];
        float dot = sv.x * dv.x + sv.y * dv.y + sv.z * dv.z + sv.w * dv.w;
#pragma unroll
        for (int o = 16; o; o >>= 1) dot += __shfl_xor_sync(0xffffffffu, dot, o);
        float e = b * dot * invd * g_inv_norm[s];   // identical in all lanes

        float m_new = fmaxf(m_w, e);
        float scale = __expf(m_w - m_new);          // 0 on first edge (m_w=-FLT_MAX)
        float w     = __expf(e - m_new);
        s_w   = s_w * scale + w;
        acc.x = acc.x * scale + w * sv.x;
        acc.y = acc.y * scale + w * sv.y;
        acc.z = acc.z * scale + w * sv.z;
        acc.w = acc.w * scale + w * sv.w;
        m_w = m_new;
    }

    __shared__ float sm[4], ss[4];
    __shared__ float sacc[4][D_FEAT];
    if (lane == 0) { sm[warp] = m_w; ss[warp] = s_w; }
    __syncthreads();

    float m = fmaxf(fmaxf(sm[0], sm[1]), fmaxf(sm[2], sm[3]));   // finite: deg>0
    float stot = ss[0] * __expf(sm[0] - m) + ss[1] * __expf(sm[1] - m)
               + ss[2] * __expf(sm[2] - m) + ss[3] * __expf(sm[3] - m);

    float f = __expf(m_w - m);             // 0 for warps with no edges
    sacc[warp][lane * 4 + 0] = acc.x * f;
    sacc[warp][lane * 4 + 1] = acc.y * f;
    sacc[warp][lane * 4 + 2] = acc.z * f;
    sacc[warp][lane * 4 + 3] = acc.w * f;
    __syncthreads();

    float r = 1.0f / stot;
    float o = (sacc[0][tid] + sacc[1][tid] + sacc[2][tid] + sacc[3][tid]) * r;
    out[(size_t)n * D_FEAT + tid] = o;
}

// ---------------- launch ----------------
extern "C" void kernel_launch(void* const* d_in, const int* in_sizes, int n_in,
                              void* d_out, int out_size) {
    const float* feat = (const float*)d_in[0];
    const void*  src  = d_in[1];
    const void*  dst  = d_in[2];
    const float* beta = (const float*)d_in[3];
    float*       out  = (float*)d_out;

    detect_kernel<<<1, 32>>>((const unsigned int*)dst);
    {
        int threads = 256;
        int blocks  = (N_NODES * 32 + threads - 1) / threads;
        norm_kernel<<<blocks, threads>>>(feat);
    }
    hist_kernel<<<(N_EDGES + 255) / 256, 256>>>(dst);
    scan_kernel<<<1, 1024>>>();
    scatter_kernel<<<(N_EDGES + 255) / 256, 256>>>(src, dst);
    agnn_fused_kernel<<<N_NODES, 128>>>(feat, beta, out);
}

// round 7
// speedup vs baseline: 1.3555x; 1.1628x over previous
#include <cuda_runtime.h>
#include <math.h>
#include <float.h>

#define N_NODES 10000
#define N_EDGES 640000
#define D_FEAT  128

// ---------------- device scratch (no allocations allowed) ----------------
__device__ __align__(16) float g_inv_norm[N_NODES];
__device__ __align__(16) int   g_count[N_NODES];
__device__ __align__(16) int   g_offsets[N_NODES + 1];
__device__ __align__(16) int   g_cursor[N_NODES];
__device__ __align__(16) int   g_src_sorted[N_EDGES];
__device__ int g_is64;

// index loader: works for int32 or int64 source data
__device__ __forceinline__ int load_idx(const void* p, int i, int is64) {
    if (is64) return (int)((const long long*)p)[i];
    return ((const int*)p)[i];
}

// ---------------- K1: zero histogram + detect index width ----------------
__global__ void init_kernel(const unsigned int* __restrict__ raw) {
    int gid = blockIdx.x * blockDim.x + threadIdx.x;
    if (gid < N_NODES / 4) ((int4*)g_count)[gid] = make_int4(0, 0, 0, 0);
    if (blockIdx.x == 0 && threadIdx.x < 32) {
        int lane = threadIdx.x;
        unsigned int local = 0;
#pragma unroll
        for (int k = 0; k < 32; k++) local |= raw[2 * (lane + 32 * k) + 1];
        unsigned int any = __any_sync(0xffffffffu, local != 0u);
        if (lane == 0) g_is64 = any ? 0 : 1;
    }
}

// ---------------- K2: fused node norms + dst histogram ----------------
#define NORM_BLOCKS 1250   // 1250 blocks * 8 warps = 10000 warps (one per node)
#define HIST_BLOCKS 625    // 625 blocks * 256 thr * 4 edges = 640000
__global__ void norm_hist_kernel(const float* __restrict__ feat,
                                 const void* __restrict__ dst) {
    if (blockIdx.x < NORM_BLOCKS) {
        int gw   = (blockIdx.x * 256 + threadIdx.x) >> 5;
        int lane = threadIdx.x & 31;
        if (gw >= N_NODES) return;
        float4 v = ((const float4*)(feat + (size_t)gw * D_FEAT))[lane];
        float ss = v.x * v.x + v.y * v.y + v.z * v.z + v.w * v.w;
#pragma unroll
        for (int o = 16; o; o >>= 1) ss += __shfl_xor_sync(0xffffffffu, ss, o);
        if (lane == 0) {
            float nrm = sqrtf(ss);
            g_inv_norm[gw] = 1.0f / fmaxf(nrm, 1e-12f);
        }
    } else {
        int b  = blockIdx.x - NORM_BLOCKS;
        int e0 = (b * 256 + threadIdx.x) * 4;
        int is64 = g_is64;
#pragma unroll
        for (int k = 0; k < 4; k++) {
            int i = e0 + k;
            if (i < N_EDGES) {
                int d = load_idx(dst, i, is64);
                if ((unsigned)d < (unsigned)N_NODES) atomicAdd(&g_count[d], 1);
            }
        }
    }
}

// ---------------- K3: vectorized exclusive scan (1 block, 640 threads) ----------------
// 625 active threads x 16 elements (int4 loads/stores); 10000 = 625*16 exactly.
__global__ void scan_kernel() {
    __shared__ int wt[21];                 // wt[0]=0 pad; wt[1..20]=warp totals
    int tid  = threadIdx.x;
    int lane = tid & 31;
    int warp = tid >> 5;
    int base = tid * 16;
    bool active = (base < N_NODES);        // tid < 625

    int v[16];
    int tot = 0;
    if (active) {
        const int4* p = (const int4*)(g_count + base);
#pragma unroll
        for (int q = 0; q < 4; q++) {
            int4 t = p[q];
            v[4 * q + 0] = t.x; v[4 * q + 1] = t.y;
            v[4 * q + 2] = t.z; v[4 * q + 3] = t.w;
            tot += t.x + t.y + t.z + t.w;
        }
    }

    int x = tot;
#pragma unroll
    for (int off = 1; off < 32; off <<= 1) {
        int y = __shfl_up_sync(0xffffffffu, x, off);
        if (lane >= off) x += y;
    }
    if (tid == 0) wt[0] = 0;
    if (lane == 31) wt[warp + 1] = x;
    __syncthreads();
    if (warp == 0) {
        int w = (lane < 20) ? wt[lane + 1] : 0;
#pragma unroll
        for (int off = 1; off < 32; off <<= 1) {
            int y = __shfl_up_sync(0xffffffffu, w, off);
            if (lane >= off) w += y;
        }
        if (lane < 20) wt[lane + 1] = w;
    }
    __syncthreads();

    int run = wt[warp] + (x - tot);
    if (active) {
        int r[16];
#pragma unroll
        for (int k = 0; k < 16; k++) { r[k] = run; run += v[k]; }
        int4* po = (int4*)(g_offsets + base);
        int4* pc = (int4*)(g_cursor  + base);
#pragma unroll
        for (int q = 0; q < 4; q++) {
            int4 t = make_int4(r[4*q], r[4*q+1], r[4*q+2], r[4*q+3]);
            po[q] = t; pc[q] = t;
        }
    }
    if (tid == 0) g_offsets[N_NODES] = wt[20];
}

// ---------------- K4: scatter edges into dst-sorted order (4 edges/thread) ----------------
__global__ void scatter_kernel(const void* __restrict__ src,
                               const void* __restrict__ dst) {
    int e0 = (blockIdx.x * blockDim.x + threadIdx.x) * 4;
    int is64 = g_is64;
#pragma unroll
    for (int k = 0; k < 4; k++) {
        int i = e0 + k;
        if (i < N_EDGES) {
            int d = load_idx(dst, i, is64);
            if ((unsigned)d < (unsigned)N_NODES) {
                int pos = atomicAdd(&g_cursor[d], 1);
                if ((unsigned)pos < (unsigned)N_EDGES)
                    g_src_sorted[pos] = load_idx(src, i, is64);
            }
        }
    }
}

// ---------------- K5: single-pass online-softmax attention ----------------
// 128 threads (4 warps = 8 half-warp edge slots) per dst node. Each half-warp
// streams one edge per iteration (lane hl holds dims 8*hl..8*hl+7), so each
// warp reduces TWO edges in one 4-step shuffle chain.
__global__ void __launch_bounds__(128) agnn_fused_kernel(const float* __restrict__ feat,
                                                         const float* __restrict__ beta,
                                                         float* __restrict__ out) {
    int n    = blockIdx.x;
    int tid  = threadIdx.x;
    int warp = tid >> 5;
    int lane = tid & 31;
    int half = lane >> 4;
    int hl   = lane & 15;
    int slot = warp * 2 + half;            // 0..7

    int start = g_offsets[n];
    int end   = g_offsets[n + 1];
    if (end == start) {                    // out poisoned; must write zeros
        out[(size_t)n * D_FEAT + tid] = 0.0f;
        return;
    }

    float invd = g_inv_norm[n];
    float b    = beta[0];
    const float4* drow = (const float4*)(feat + (size_t)n * D_FEAT);
    float4 dv0 = drow[hl * 2];
    float4 dv1 = drow[hl * 2 + 1];

    float  m_w = -FLT_MAX;
    float  s_w = 0.0f;
    float4 a0  = make_float4(0.f, 0.f, 0.f, 0.f);
    float4 a1  = make_float4(0.f, 0.f, 0.f, 0.f);

    int j = start + slot;
    int nIter = (end - start - warp * 2 + 7) >> 3;   // >= both halves' trip counts
    if (nIter < 0) nIter = 0;

    for (int it = 0; it < nIter; it++, j += 8) {
        bool valid = (j < end);
        int s = valid ? g_src_sorted[j] : n;         // dummy row (L2-hot) when invalid
        const float4* srow = (const float4*)(feat + (size_t)s * D_FEAT);
        float4 s0 = srow[hl * 2];
        float4 s1 = srow[hl * 2 + 1];
        float dot = s0.x * dv0.x + s0.y * dv0.y + s0.z * dv0.z + s0.w * dv0.w
                  + s1.x * dv1.x + s1.y * dv1.y + s1.z * dv1.z + s1.w * dv1.w;
#pragma unroll
        for (int o = 8; o; o >>= 1) dot += __shfl_xor_sync(0xffffffffu, dot, o);
        if (valid) {
            float e = b * dot * invd * g_inv_norm[s];
            float m_new = fmaxf(m_w, e);
            float scale = __expf(m_w - m_new);       // 0 on first edge
            float w     = __expf(e - m_new);
            s_w  = s_w * scale + w;
            a0.x = a0.x * scale + w * s0.x;  a0.y = a0.y * scale + w * s0.y;
            a0.z = a0.z * scale + w * s0.z;  a0.w = a0.w * scale + w * s0.w;
            a1.x = a1.x * scale + w * s1.x;  a1.y = a1.y * scale + w * s1.y;
            a1.z = a1.z * scale + w * s1.z;  a1.w = a1.w * scale + w * s1.w;
            m_w = m_new;
        }
    }

    __shared__ float sm[8], ssum[8];
    __shared__ float sacc[8][132];                   // pad 132: conflict-free column read
    if (hl == 0) { sm[slot] = m_w; ssum[slot] = s_w; }
    __syncthreads();

    float m = sm[0];
#pragma unroll
    for (int k = 1; k < 8; k++) m = fmaxf(m, sm[k]); // finite: deg > 0
    float stot = 0.0f;
#pragma unroll
    for (int k = 0; k < 8; k++) stot += ssum[k] * __expf(sm[k] - m);

    float f = __expf(m_w - m);                       // 0 for empty slots
    float* dp = &sacc[slot][hl * 8];
    dp[0] = a0.x * f; dp[1] = a0.y * f; dp[2] = a0.z * f; dp[3] = a0.w * f;
    dp[4] = a1.x * f; dp[5] = a1.y * f; dp[6] = a1.z * f; dp[7] = a1.w * f;
    __syncthreads();

    float o = 0.0f;
#pragma unroll
    for (int k = 0; k < 8; k++) o += sacc[k][tid];
    out[(size_t)n * D_FEAT + tid] = o * (1.0f / stot);
}

// ---------------- launch ----------------
extern "C" void kernel_launch(void* const* d_in, const int* in_sizes, int n_in,
                              void* d_out, int out_size) {
    const float* feat = (const float*)d_in[0];
    const void*  src  = d_in[1];
    const void*  dst  = d_in[2];
    const float* beta = (const float*)d_in[3];
    float*       out  = (float*)d_out;

    init_kernel<<<3, 1024>>>((const unsigned int*)dst);
    norm_hist_kernel<<<NORM_BLOCKS + HIST_BLOCKS, 256>>>(feat, dst);
    scan_kernel<<<1, 640>>>();
    scatter_kernel<<<(N_EDGES / 4 + 255) / 256, 256>>>(src, dst);
    agnn_fused_kernel<<<N_NODES, 128>>>(feat, beta, out);
}

// round 8
// speedup vs baseline: 1.5029x; 1.1087x over previous
#include <cuda_runtime.h>
#include <math.h>
#include <float.h>

#define N_NODES 10000
#define N_EDGES 640000
#define D_FEAT  128

// ---------------- device scratch (no allocations allowed) ----------------
__device__ __align__(16) float g_inv_norm[N_NODES];
__device__ __align__(16) int   g_count[N_NODES];
__device__ __align__(16) int   g_offsets[N_NODES + 1];
__device__ __align__(16) int   g_cursor[N_NODES];
__device__ __align__(16) int   g_src_sorted[N_EDGES];
__device__ int g_is64;

// index loader: works for int32 or int64 source data
__device__ __forceinline__ int load_idx(const void* p, int i, int is64) {
    if (is64) return (int)((const long long*)p)[i];
    return ((const int*)p)[i];
}

// ---------------- K1: zero histogram + detect index width ----------------
__global__ void init_kernel(const unsigned int* __restrict__ raw) {
    int gid = blockIdx.x * blockDim.x + threadIdx.x;
    if (gid < N_NODES / 4) ((int4*)g_count)[gid] = make_int4(0, 0, 0, 0);
    if (blockIdx.x == 0 && threadIdx.x < 32) {
        int lane = threadIdx.x;
        unsigned int local = 0;
#pragma unroll
        for (int k = 0; k < 32; k++) local |= raw[2 * (lane + 32 * k) + 1];
        unsigned int any = __any_sync(0xffffffffu, local != 0u);
        if (lane == 0) g_is64 = any ? 0 : 1;
    }
}

// ---------------- K2: fused node norms + dst histogram ----------------
#define NORM_BLOCKS 1250   // 1250 blocks * 8 warps = 10000 warps (one per node)
#define HIST_BLOCKS 2500   // 2500 blocks * 256 thr * 1 edge = 640000
__global__ void norm_hist_kernel(const float* __restrict__ feat,
                                 const void* __restrict__ dst) {
    if (blockIdx.x < NORM_BLOCKS) {
        int gw   = (blockIdx.x * 256 + threadIdx.x) >> 5;
        int lane = threadIdx.x & 31;
        if (gw >= N_NODES) return;
        float4 v = ((const float4*)(feat + (size_t)gw * D_FEAT))[lane];
        float ss = v.x * v.x + v.y * v.y + v.z * v.z + v.w * v.w;
#pragma unroll
        for (int o = 16; o; o >>= 1) ss += __shfl_xor_sync(0xffffffffu, ss, o);
        if (lane == 0) {
            float nrm = sqrtf(ss);
            g_inv_norm[gw] = 1.0f / fmaxf(nrm, 1e-12f);
        }
    } else {
        int i = (blockIdx.x - NORM_BLOCKS) * 256 + threadIdx.x;
        if (i < N_EDGES) {
            int d = load_idx(dst, i, g_is64);
            if ((unsigned)d < (unsigned)N_NODES) atomicAdd(&g_count[d], 1);
        }
    }
}

// ---------------- K3: vectorized exclusive scan (1 block, 640 threads) ----------------
// 625 active threads x 16 elements (int4 loads/stores); 10000 = 625*16 exactly.
__global__ void scan_kernel() {
    __shared__ int wt[21];                 // wt[0]=0 pad; wt[1..20]=warp totals
    int tid  = threadIdx.x;
    int lane = tid & 31;
    int warp = tid >> 5;
    int base = tid * 16;
    bool active = (base < N_NODES);        // tid < 625

    int v[16];
    int tot = 0;
    if (active) {
        const int4* p = (const int4*)(g_count + base);
#pragma unroll
        for (int q = 0; q < 4; q++) {
            int4 t = p[q];
            v[4 * q + 0] = t.x; v[4 * q + 1] = t.y;
            v[4 * q + 2] = t.z; v[4 * q + 3] = t.w;
            tot += t.x + t.y + t.z + t.w;
        }
    }

    int x = tot;
#pragma unroll
    for (int off = 1; off < 32; off <<= 1) {
        int y = __shfl_up_sync(0xffffffffu, x, off);
        if (lane >= off) x += y;
    }
    if (tid == 0) wt[0] = 0;
    if (lane == 31) wt[warp + 1] = x;
    __syncthreads();
    if (warp == 0) {
        int w = (lane < 20) ? wt[lane + 1] : 0;
#pragma unroll
        for (int off = 1; off < 32; off <<= 1) {
            int y = __shfl_up_sync(0xffffffffu, w, off);
            if (lane >= off) w += y;
        }
        if (lane < 20) wt[lane + 1] = w;
    }
    __syncthreads();

    int run = wt[warp] + (x - tot);
    if (active) {
        int r[16];
#pragma unroll
        for (int k = 0; k < 16; k++) { r[k] = run; run += v[k]; }
        int4* po = (int4*)(g_offsets + base);
        int4* pc = (int4*)(g_cursor  + base);
#pragma unroll
        for (int q = 0; q < 4; q++) {
            int4 t = make_int4(r[4*q], r[4*q+1], r[4*q+2], r[4*q+3]);
            po[q] = t; pc[q] = t;
        }
    }
    if (tid == 0) g_offsets[N_NODES] = wt[20];
}

// ---------------- K4: scatter edges into dst-sorted order (1 edge/thread) ----------------
// Max thread count for MLP: atomic latency (~318cy) hidden by outstanding ops.
__global__ void scatter_kernel(const void* __restrict__ src,
                               const void* __restrict__ dst) {
    int i = blockIdx.x * blockDim.x + threadIdx.x;
    if (i < N_EDGES) {
        int is64 = g_is64;
        int d = load_idx(dst, i, is64);
        if ((unsigned)d < (unsigned)N_NODES) {
            int pos = atomicAdd(&g_cursor[d], 1);
            if ((unsigned)pos < (unsigned)N_EDGES)
                g_src_sorted[pos] = load_idx(src, i, is64);
        }
    }
}

// ---------------- K5: single-pass online-softmax attention (pipelined) ----------------
// 128 threads (4 warps = 8 half-warp edge slots) per dst node. Lane hl holds
// dims 8*hl..8*hl+7. Next edge's index/row/norm prefetched before the current
// edge's SHFL-reduce + exp chain, hiding the ~234cy L2 row fetch.
__global__ void __launch_bounds__(128) agnn_fused_kernel(const float* __restrict__ feat,
                                                         const float* __restrict__ beta,
                                                         float* __restrict__ out) {
    int n    = blockIdx.x;
    int tid  = threadIdx.x;
    int warp = tid >> 5;
    int lane = tid & 31;
    int half = lane >> 4;
    int hl   = lane & 15;
    int slot = warp * 2 + half;            // 0..7

    int start = g_offsets[n];
    int end   = g_offsets[n + 1];
    if (end == start) {                    // out poisoned; must write zeros
        out[(size_t)n * D_FEAT + tid] = 0.0f;
        return;
    }

    float invd = g_inv_norm[n];
    float b    = beta[0];
    const float4* drow = (const float4*)(feat + (size_t)n * D_FEAT);
    float4 dv0 = drow[hl * 2];
    float4 dv1 = drow[hl * 2 + 1];

    float  m_w = -FLT_MAX;
    float  s_w = 0.0f;
    float4 a0  = make_float4(0.f, 0.f, 0.f, 0.f);
    float4 a1  = make_float4(0.f, 0.f, 0.f, 0.f);

    int j = start + slot;
    int nIter = (end - start - warp * 2 + 7) >> 3;   // >= both halves' trip counts
    if (nIter < 0) nIter = 0;

    // prologue prefetch
    int   s_nx  = (j < end) ? g_src_sorted[j] : n;
    float in_nx = g_inv_norm[s_nx];
    const float4* prow = (const float4*)(feat + (size_t)s_nx * D_FEAT);
    float4 p0 = prow[hl * 2];
    float4 p1 = prow[hl * 2 + 1];

    for (int it = 0; it < nIter; it++) {
        bool  valid = (j < end);
        float4 s0 = p0, s1 = p1;
        float in_s = in_nx;
        j += 8;

        // issue next iteration's loads before the reduce chain
        int jn = j;
        s_nx  = (jn < end) ? g_src_sorted[jn] : n;
        in_nx = g_inv_norm[s_nx];
        prow  = (const float4*)(feat + (size_t)s_nx * D_FEAT);
        p0 = prow[hl * 2];
        p1 = prow[hl * 2 + 1];

        float dot = s0.x * dv0.x + s0.y * dv0.y + s0.z * dv0.z + s0.w * dv0.w
                  + s1.x * dv1.x + s1.y * dv1.y + s1.z * dv1.z + s1.w * dv1.w;
#pragma unroll
        for (int o = 8; o; o >>= 1) dot += __shfl_xor_sync(0xffffffffu, dot, o);
        if (valid) {
            float e = b * dot * invd * in_s;
            float m_new = fmaxf(m_w, e);
            float scale = __expf(m_w - m_new);       // 0 on first edge
            float w     = __expf(e - m_new);
            s_w  = s_w * scale + w;
            a0.x = a0.x * scale + w * s0.x;  a0.y = a0.y * scale + w * s0.y;
            a0.z = a0.z * scale + w * s0.z;  a0.w = a0.w * scale + w * s0.w;
            a1.x = a1.x * scale + w * s1.x;  a1.y = a1.y * scale + w * s1.y;
            a1.z = a1.z * scale + w * s1.z;  a1.w = a1.w * scale + w * s1.w;
            m_w = m_new;
        }
    }

    __shared__ float sm[8], ssum[8];
    __shared__ float sacc[8][132];                   // pad 132: conflict-free column read
    if (hl == 0) { sm[slot] = m_w; ssum[slot] = s_w; }
    __syncthreads();

    float m = sm[0];
#pragma unroll
    for (int k = 1; k < 8; k++) m = fmaxf(m, sm[k]); // finite: deg > 0
    float stot = 0.0f;
#pragma unroll
    for (int k = 0; k < 8; k++) stot += ssum[k] * __expf(sm[k] - m);

    float f = __expf(m_w - m);                       // 0 for empty slots
    float* dp = &sacc[slot][hl * 8];
    dp[0] = a0.x * f; dp[1] = a0.y * f; dp[2] = a0.z * f; dp[3] = a0.w * f;
    dp[4] = a1.x * f; dp[5] = a1.y * f; dp[6] = a1.z * f; dp[7] = a1.w * f;
    __syncthreads();

    float o = 0.0f;
#pragma unroll
    for (int k = 0; k < 8; k++) o += sacc[k][tid];
    out[(size_t)n * D_FEAT + tid] = o * (1.0f / stot);
}

// ---------------- launch ----------------
extern "C" void kernel_launch(void* const* d_in, const int* in_sizes, int n_in,
                              void* d_out, int out_size) {
    const float* feat = (const float*)d_in[0];
    const void*  src  = d_in[1];
    const void*  dst  = d_in[2];
    const float* beta = (const float*)d_in[3];
    float*       out  = (float*)d_out;

    init_kernel<<<3, 1024>>>((const unsigned int*)dst);
    norm_hist_kernel<<<NORM_BLOCKS + HIST_BLOCKS, 256>>>(feat, dst);
    scan_kernel<<<1, 640>>>();
    scatter_kernel<<<(N_EDGES + 255) / 256, 256>>>(src, dst);
    agnn_fused_kernel<<<N_NODES, 128>>>(feat, beta, out);
}